// round 12
// baseline (speedup 1.0000x reference)
#include <cuda_runtime.h>
#include <cuda_bf16.h>
#include <cstdint>

// Problem constants
#define S 8192
#define E 64
#define D 4096
#define CAP 128
#define SE 524288          // S*E
#define SEC 67108864LL     // S*E*CAP

#define GEMM_BLOCKS 512
#define ZB_BLOCKS 80
#define TOTAL_BLOCKS (GEMM_BLOCKS + ZB_BLOCKS)   // 592 = 148*4 -> fully resident
#define K3_SMEM_CAP 4096
#define XST 68             // padded smem row stride (floats)

// ---------------- device scratch (no allocations allowed) ----------------
__device__ float g_part[4 * SE];        // split-K partial logits (8 MB)
__device__ int   g_assign[S];
__device__ float g_topgate[S];
__device__ int   g_slotpack[S];         // (e<<7)|slot if kept, else -1
__device__ float g_cspart[512 * 64];
__device__ int   g_counts[64];
__device__ float g_laux;
__device__ unsigned long long g_bar1;   // monotonic ticket counters (replay-safe)
__device__ unsigned long long g_bar2;

// ---------------- f32x2 helpers ----------------
__device__ __forceinline__ unsigned long long packdup(float a) {
    unsigned long long r;
    asm("mov.b64 %0, {%1, %2};" : "=l"(r) : "f"(a), "f"(a));
    return r;
}
__device__ __forceinline__ void fma2(unsigned long long& d, unsigned long long a, unsigned long long b) {
    asm("fma.rn.f32x2 %0, %1, %2, %0;" : "+l"(d) : "l"(a), "l"(b));
}
__device__ __forceinline__ void unpack2(unsigned long long v, float& lo, float& hi) {
    asm("mov.b64 {%0, %1}, %2;" : "=f"(lo), "=f"(hi) : "l"(v));
}

// Device-wide barrier over the 512 GEMM blocks. Monotonic counter: launch n
// consumes tickets [512n, 512(n+1)) so the release target is (t/512+1)*512 —
// correct across arbitrarily many graph replays with no reset.
__device__ __forceinline__ void grid_bar512(unsigned long long* ctr) {
    __syncthreads();
    if (threadIdx.x == 0) {
        __threadfence();
        unsigned long long t = atomicAdd(ctr, 1ULL);
        unsigned long long target = (t / 512ULL + 1ULL) * 512ULL;
        while (*((volatile unsigned long long*)ctr) < target) { __nanosleep(64); }
        __threadfence();
    }
    __syncthreads();
}

// Phases are sequential per block -> share smem via union.
union SmemU {
    struct { float xs[2][32][XST]; float ws[2][32][XST]; } g;          // 34816 B
    struct { float cs[64]; int cnt[64]; } gate;
    struct {
        unsigned bits[K3_SMEM_CAP];
        unsigned short tok[K3_SMEM_CAP];
        int red[4]; int weq[4]; int wkp[4]; int ne;
        float ps[128]; float contrib[64];
    } sel;                                                              // ~25.4 KB
};

// ==========================================================================
// K1 (persistent): blocks [0,512): GEMM -> bar -> gate -> bar -> select ->
//                  join zero-fill (own the top 32% of the output).
//                  blocks [512,592): stream-zero the bottom 68% from t=0.
// ==========================================================================
__global__ __launch_bounds__(128, 4) void k1_mega(const float* __restrict__ x,
                                                  const float* __restrict__ w,
                                                  const float* __restrict__ noise,
                                                  float* __restrict__ out,
                                                  long long out_n) {
    const int tid = threadIdx.x;
    const int bid = blockIdx.x;
    const int lane = tid & 31;
    const int wid = tid >> 5;

    const long long TOT4 = out_n >> 2;
    const long long WSH = (TOT4 * 17LL) / 25LL;      // writer share (~68%)
    float4* const o4 = reinterpret_cast<float4*>(out);
    const float4 zf4 = make_float4(0.f, 0.f, 0.f, 0.f);

    if (bid >= GEMM_BLOCKS) {
        // ---------------- dedicated writer blocks ----------------
        const int zb = bid - GEMM_BLOCKS;            // 0..79
        const long long stride = (long long)ZB_BLOCKS * 128;
        for (long long i = (long long)zb * 128 + tid; i < WSH; i += stride)
            __stcs(o4 + i, zf4);
        return;
    }

    __shared__ __align__(16) SmemU sm;

    // =================== phase 1: split-K GEMM ===================
    if (bid == 0 && tid == 0) {
        for (int e = 0; e < 64; e++) g_counts[e] = 0;
    }
    {
        const int kp = bid & 3;
        const int tb = bid >> 2;
        const int t0 = tb * 64;
        const int kbase = kp * 1024;
        const int tm = tid & 7;
        const int tn = tid >> 3;

        {
#pragma unroll
            for (int r = 0; r < 4; r++) {
                int idx = tid + r * 128;
                int row = idx >> 3;
                int kq  = (idx & 7) << 2;
                float4 xv = *reinterpret_cast<const float4*>(&x[(size_t)(t0 + row) * D + kbase + kq]);
                sm.g.xs[0][kq + 0][row] = xv.x; sm.g.xs[0][kq + 1][row] = xv.y;
                sm.g.xs[0][kq + 2][row] = xv.z; sm.g.xs[0][kq + 3][row] = xv.w;
                float4 wv = *reinterpret_cast<const float4*>(&w[(size_t)row * D + kbase + kq]);
                sm.g.ws[0][kq + 0][row] = wv.x; sm.g.ws[0][kq + 1][row] = wv.y;
                sm.g.ws[0][kq + 2][row] = wv.z; sm.g.ws[0][kq + 3][row] = wv.w;
            }
        }
        __syncthreads();

        unsigned long long acc[4][4];
#pragma unroll
        for (int i = 0; i < 4; i++)
#pragma unroll
            for (int j = 0; j < 4; j++) acc[i][j] = 0ULL;

        const int NKB = 32;
        for (int kb = 0; kb < NKB; kb++) {
            const int buf = kb & 1;
            float4 px[4], pw[4];
            if (kb + 1 < NKB) {
                const int k0 = kbase + (kb + 1) * 32;
#pragma unroll
                for (int r = 0; r < 4; r++) {
                    int idx = tid + r * 128;
                    int row = idx >> 3;
                    int kq  = (idx & 7) << 2;
                    px[r] = *reinterpret_cast<const float4*>(&x[(size_t)(t0 + row) * D + k0 + kq]);
                    pw[r] = *reinterpret_cast<const float4*>(&w[(size_t)row * D + k0 + kq]);
                }
            }

            const float* xr = &sm.g.xs[buf][0][8 * tm];
            const float* wr = &sm.g.ws[buf][0][4 * tn];
            ulonglong2 A0 = *reinterpret_cast<const ulonglong2*>(xr);
            ulonglong2 A1 = *reinterpret_cast<const ulonglong2*>(xr + 4);
            float4     Wc = *reinterpret_cast<const float4*>(wr);

#pragma unroll
            for (int kk = 0; kk < 32; kk++) {
                ulonglong2 B0, B1; float4 Wn;
                if (kk < 31) {
                    const float* xn = xr + (kk + 1) * XST;
                    const float* wn = wr + (kk + 1) * XST;
                    B0 = *reinterpret_cast<const ulonglong2*>(xn);
                    B1 = *reinterpret_cast<const ulonglong2*>(xn + 4);
                    Wn = *reinterpret_cast<const float4*>(wn);
                }
                unsigned long long wp;
                wp = packdup(Wc.x);
                fma2(acc[0][0], A0.x, wp); fma2(acc[1][0], A0.y, wp);
                fma2(acc[2][0], A1.x, wp); fma2(acc[3][0], A1.y, wp);
                wp = packdup(Wc.y);
                fma2(acc[0][1], A0.x, wp); fma2(acc[1][1], A0.y, wp);
                fma2(acc[2][1], A1.x, wp); fma2(acc[3][1], A1.y, wp);
                wp = packdup(Wc.z);
                fma2(acc[0][2], A0.x, wp); fma2(acc[1][2], A0.y, wp);
                fma2(acc[2][2], A1.x, wp); fma2(acc[3][2], A1.y, wp);
                wp = packdup(Wc.w);
                fma2(acc[0][3], A0.x, wp); fma2(acc[1][3], A0.y, wp);
                fma2(acc[2][3], A1.x, wp); fma2(acc[3][3], A1.y, wp);
                if (kk < 31) { A0 = B0; A1 = B1; Wc = Wn; }
            }

            if (kb + 1 < NKB) {
                const int nb = buf ^ 1;
#pragma unroll
                for (int r = 0; r < 4; r++) {
                    int idx = tid + r * 128;
                    int row = idx >> 3;
                    int kq  = (idx & 7) << 2;
                    sm.g.xs[nb][kq + 0][row] = px[r].x; sm.g.xs[nb][kq + 1][row] = px[r].y;
                    sm.g.xs[nb][kq + 2][row] = px[r].z; sm.g.xs[nb][kq + 3][row] = px[r].w;
                    sm.g.ws[nb][kq + 0][row] = pw[r].x; sm.g.ws[nb][kq + 1][row] = pw[r].y;
                    sm.g.ws[nb][kq + 2][row] = pw[r].z; sm.g.ws[nb][kq + 3][row] = pw[r].w;
                }
            }
            __syncthreads();
        }

        float* part = &g_part[(size_t)kp * SE];
#pragma unroll
        for (int i = 0; i < 4; i++) {
#pragma unroll
            for (int j = 0; j < 4; j++) {
                float lo, hi;
                unpack2(acc[i][j], lo, hi);
                int t = t0 + 8 * tm + 2 * i;
                int e = 4 * tn + j;
                part[(size_t)t * E + e]       = lo;
                part[(size_t)(t + 1) * E + e] = hi;
            }
        }
    }

    grid_bar512(&g_bar1);

    // =================== phase 2: gate (16 tokens/block) ===================
    {
        if (tid < 64) { sm.gate.cs[tid] = 0.f; sm.gate.cnt[tid] = 0; }
        __syncthreads();

#pragma unroll
        for (int it = 0; it < 4; it++) {
            const int t = bid * 16 + it * 4 + wid;
            const size_t b = (size_t)t * E;
            float l0 = 0.f, l1 = 0.f;
#pragma unroll
            for (int p = 0; p < 4; p++) {
                l0 += g_part[(size_t)p * SE + b + lane];
                l1 += g_part[(size_t)p * SE + b + 32 + lane];
            }
            float bv; int bi;
            if (l0 >= l1) { bv = l0; bi = lane; } else { bv = l1; bi = lane + 32; }
#pragma unroll
            for (int o = 16; o; o >>= 1) {
                float ov = __shfl_xor_sync(0xFFFFFFFFu, bv, o);
                int   oi = __shfl_xor_sync(0xFFFFFFFFu, bi, o);
                if (ov > bv || (ov == bv && oi < bi)) { bv = ov; bi = oi; }
            }
            float e0 = __expf(l0 - bv), e1 = __expf(l1 - bv);
            float z = e0 + e1;
#pragma unroll
            for (int o = 16; o; o >>= 1) z += __shfl_xor_sync(0xFFFFFFFFu, z, o);
            float inv = 1.0f / z;

            atomicAdd(&sm.gate.cs[lane],      e0 * inv);
            atomicAdd(&sm.gate.cs[lane + 32], e1 * inv);
            if (lane == 0) {
                g_assign[t]   = bi;
                g_topgate[t]  = inv;
                g_slotpack[t] = -1;
                atomicAdd(&sm.gate.cnt[bi], 1);
            }
        }
        __syncthreads();
        if (tid < 64) {
            g_cspart[bid * 64 + tid] = sm.gate.cs[tid];
            if (sm.gate.cnt[tid]) atomicAdd(&g_counts[tid], sm.gate.cnt[tid]);
        }
    }

    grid_bar512(&g_bar2);

    // =================== phase 3: select (blocks 0..63), laux (64) ==========
    if (bid == 64) {
        const int eidx = tid >> 1, q = tid & 1;
        float s = 0.f;
        for (int bkt = q * 256; bkt < q * 256 + 256; bkt++) s += g_cspart[bkt * 64 + eidx];
        sm.sel.ps[tid] = s;
        __syncthreads();
        if (tid < 64) {
            float me = (sm.sel.ps[tid * 2] + sm.sel.ps[tid * 2 + 1]) / (float)S;
            float ce = (float)g_counts[tid] / (float)S;
            sm.sel.contrib[tid] = me * ce * (float)E;
        }
        __syncthreads();
        if (tid == 0) {
            float l = 0.f;
            for (int i = 0; i < 64; i++) l += sm.sel.contrib[i];
            g_laux = l;
        }
        __syncthreads();
    } else if (bid < 64) {
        const int e = bid;

        // ---- pass 1: ordered compaction ----
        int base = 0;
        for (int c0 = 0; c0 < S; c0 += 128) {
            const int t = c0 + tid;
            const bool a = (g_assign[t] == e);
            unsigned b = 0u;
            if (a) b = __float_as_uint(noise[(size_t)t * E + e]);
            unsigned bal = __ballot_sync(0xFFFFFFFFu, a);
            if (lane == 0) sm.sel.red[wid] = __popc(bal);
            __syncthreads();
            int off = 0;
            for (int i = 0; i < wid; i++) off += sm.sel.red[i];
            int tot = 0;
#pragma unroll
            for (int i = 0; i < 4; i++) tot += sm.sel.red[i];
            if (a) {
                int pos = base + off + __popc(bal & ((1u << lane) - 1u));
                if (pos < K3_SMEM_CAP) {
                    sm.sel.bits[pos] = b;
                    sm.sel.tok[pos]  = (unsigned short)t;
                }
            }
            base += tot;
            __syncthreads();
        }
        if (tid == 0) sm.sel.ne = base;
        __syncthreads();
        const int ne = sm.sel.ne;
        const bool smem_ok = (ne <= K3_SMEM_CAP);

        // ---- pass 2: binary search for threshold T ----
        unsigned lo = 0u, hi = 0x3F7FFFFFu;
        while (lo < hi) {
            unsigned mid = lo + ((hi - lo + 1) >> 1);
            int c = 0;
            if (smem_ok) {
                for (int i = tid; i < ne; i += 128) c += (sm.sel.bits[i] >= mid);
            } else {
                for (int t = tid; t < S; t += 128)
                    if (g_assign[t] == e)
                        c += (__float_as_uint(noise[(size_t)t * E + e]) >= mid);
            }
#pragma unroll
            for (int o = 16; o; o >>= 1) c += __shfl_xor_sync(0xFFFFFFFFu, c, o);
            if (lane == 0) sm.sel.red[wid] = c;
            __syncthreads();
            int tot = 0;
#pragma unroll
            for (int i = 0; i < 4; i++) tot += sm.sel.red[i];
            __syncthreads();
            if (tot >= CAP) lo = mid; else hi = mid - 1;
        }
        const unsigned T = lo;

        // ---- pass 3: count strictly-greater ----
        int kg;
        {
            int c = 0;
            const unsigned q = T + 1u;
            if (smem_ok) {
                for (int i = tid; i < ne; i += 128) c += (sm.sel.bits[i] >= q);
            } else {
                for (int t = tid; t < S; t += 128)
                    if (g_assign[t] == e)
                        c += (__float_as_uint(noise[(size_t)t * E + e]) >= q);
            }
#pragma unroll
            for (int o = 16; o; o >>= 1) c += __shfl_xor_sync(0xFFFFFFFFu, c, o);
            if (lane == 0) sm.sel.red[wid] = c;
            __syncthreads();
            int tot = 0;
#pragma unroll
            for (int i = 0; i < 4; i++) tot += sm.sel.red[i];
            kg = tot;
            __syncthreads();
        }
        const int remaining = CAP - kg;

        if (smem_ok && T > 0u) {
            // ---- pass 4 (fast): ordered walk of compacted list ----
            int kbase = 0, eqbase = 0;
            const int chunks = (ne + 127) >> 7;
            for (int ch = 0; ch < chunks; ch++) {
                const int i = ch * 128 + tid;
                const bool valid = (i < ne);
                unsigned v = valid ? sm.sel.bits[i] : 0u;
                const bool gt = valid && (v > T);
                const bool eq = valid && (v == T);

                unsigned beq = __ballot_sync(0xFFFFFFFFu, eq);
                if (lane == 0) sm.sel.weq[wid] = __popc(beq);
                __syncthreads();
                int eqoff = 0;
                for (int k = 0; k < wid; k++) eqoff += sm.sel.weq[k];
                int eqtot = 0;
#pragma unroll
                for (int k = 0; k < 4; k++) eqtot += sm.sel.weq[k];
                const int eqrank = eqbase + eqoff + __popc(beq & ((1u << lane) - 1u));

                const bool kept = gt || (eq && eqrank < remaining);
                unsigned bk = __ballot_sync(0xFFFFFFFFu, kept);
                if (lane == 0) sm.sel.wkp[wid] = __popc(bk);
                __syncthreads();
                int koff = 0;
                for (int k = 0; k < wid; k++) koff += sm.sel.wkp[k];
                int ktot = 0;
#pragma unroll
                for (int k = 0; k < 4; k++) ktot += sm.sel.wkp[k];

                if (kept) {
                    const int slot = kbase + koff + __popc(bk & ((1u << lane) - 1u));
                    g_slotpack[sm.sel.tok[i]] = (e << 7) | slot;
                }
                kbase  += ktot;
                eqbase += eqtot;
                __syncthreads();
            }
        } else {
            // ---- pass 4 (general): full scan; T==0 ties include unassigned ----
            int kbase = 0, eqbase = 0;
            for (int c0 = 0; c0 < S; c0 += 128) {
                const int t = c0 + tid;
                const bool a = (g_assign[t] == e);
                unsigned v = 0u;
                if (a) v = __float_as_uint(noise[(size_t)t * E + e]);
                const bool gt = a && (v > T);
                const bool eq = (v == T);

                unsigned beq = __ballot_sync(0xFFFFFFFFu, eq);
                if (lane == 0) sm.sel.weq[wid] = __popc(beq);
                __syncthreads();
                int eqoff = 0;
                for (int k = 0; k < wid; k++) eqoff += sm.sel.weq[k];
                int eqtot = 0;
#pragma unroll
                for (int k = 0; k < 4; k++) eqtot += sm.sel.weq[k];
                const int eqrank = eqbase + eqoff + __popc(beq & ((1u << lane) - 1u));

                const bool kept = a && (gt || (eq && eqrank < remaining));
                unsigned bk = __ballot_sync(0xFFFFFFFFu, kept);
                if (lane == 0) sm.sel.wkp[wid] = __popc(bk);
                __syncthreads();
                int koff = 0;
                for (int k = 0; k < wid; k++) koff += sm.sel.wkp[k];
                int ktot = 0;
#pragma unroll
                for (int k = 0; k < 4; k++) ktot += sm.sel.wkp[k];

                if (kept) {
                    const int slot = kbase + koff + __popc(bk & ((1u << lane) - 1u));
                    g_slotpack[t] = (e << 7) | slot;
                }
                kbase  += ktot;
                eqbase += eqtot;
                __syncthreads();
            }
        }
    }

    // =================== phase 4: join the zero-fill ===================
    {
        const long long stride = (long long)GEMM_BLOCKS * 128;
        for (long long i = WSH + (long long)bid * 128 + tid; i < TOT4; i += stride)
            __stcs(o4 + i, zf4);
    }
}

// ==========================================================================
// K5: scatter nonzeros + counts + l_aux into the zeroed output.
// ==========================================================================
__global__ __launch_bounds__(256) void k5_scatter(float* __restrict__ out, long long out_n) {
    const int g = blockIdx.x * 256 + threadIdx.x;
    if (g < S) {
        const int p = g_slotpack[g];
        if (p >= 0) {
            const long long off = ((long long)g * E + (p >> 7)) * (long long)CAP + (p & 127);
            out[1 + off]       = g_topgate[g];   // combine_weights
            out[1 + SEC + off] = 1.0f;           // dispatch_mask
        }
    } else if (g < S + 64) {
        out[1 + 2 * SEC + (g - S)] = (float)g_counts[g - S];
    } else if (g == S + 64) {
        out[0] = g_laux;
    }
}

// ==========================================================================
extern "C" void kernel_launch(void* const* d_in, const int* in_sizes, int n_in,
                              void* d_out, int out_size) {
    const float* x     = (const float*)d_in[0];
    const float* w     = (const float*)d_in[1];
    const float* noise = (const float*)d_in[2];
    float* out = (float*)d_out;
    const long long n = (long long)out_size;

    k1_mega<<<TOTAL_BLOCKS, 128>>>(x, w, noise, out, n);
    k5_scatter<<<33, 256>>>(out, n);
}

// round 13
// speedup vs baseline: 1.0539x; 1.0539x over previous
#include <cuda_runtime.h>
#include <cuda_bf16.h>
#include <cstdint>

// Problem constants
#define S 8192
#define E 64
#define D 4096
#define CAP 128
#define SE 524288          // S*E
#define SEC 67108864LL     // S*E*CAP

#define GEMM_BLOCKS 512
#define ZB_BLOCKS 80
#define TOTAL_BLOCKS (GEMM_BLOCKS + ZB_BLOCKS)   // 592 = 148*4

#define K3_SMEM_CAP 4096
#define XST 68            // padded smem row stride (floats), 16B-aligned rows

// ---------------- device scratch (no allocations allowed) ----------------
__device__ float g_part[4 * SE];        // split-K partial logits (8 MB)
__device__ int   g_assign[S];
__device__ float g_topgate[S];
__device__ float g_cspart[64 * 64];     // per-gate-block column sums
__device__ int   g_counts[64];
__device__ unsigned long long g_bar65;  // monotonic ticket counter (replay-safe)

// ---------------- f32x2 helpers ----------------
__device__ __forceinline__ unsigned long long packdup(float a) {
    unsigned long long r;
    asm("mov.b64 %0, {%1, %2};" : "=l"(r) : "f"(a), "f"(a));
    return r;
}
__device__ __forceinline__ void fma2(unsigned long long& d, unsigned long long a, unsigned long long b) {
    asm("fma.rn.f32x2 %0, %1, %2, %0;" : "+l"(d) : "l"(a), "l"(b));
}
__device__ __forceinline__ void unpack2(unsigned long long v, float& lo, float& hi) {
    asm("mov.b64 {%0, %1}, %2;" : "=f"(lo), "=f"(hi) : "l"(v));
}

// ==========================================================================
// K1: identical to the round-10 passing kernel (k1 = 219 us measured).
//     blocks [0,512): fp32 split-K GEMM; blocks [512,592): STG.128 zero-fill.
// ==========================================================================
__global__ __launch_bounds__(128, 4) void k1_fused(const float* __restrict__ x,
                                                   const float* __restrict__ w,
                                                   float* __restrict__ out,
                                                   long long out_n) {
    const int tid = threadIdx.x;

    if (blockIdx.x >= GEMM_BLOCKS) {
        const int zb = blockIdx.x - GEMM_BLOCKS;           // 0..79
        if (zb == 0 && tid == 0) {
            for (int e = 0; e < 64; e++) g_counts[e] = 0;
        }
        float4* const o4 = reinterpret_cast<float4*>(out);
        const float4 zf4 = make_float4(0.f, 0.f, 0.f, 0.f);
        const long long nv4 = out_n >> 2;
        const long long stride = (long long)ZB_BLOCKS * 128;
        for (long long i = (long long)zb * 128 + tid; i < nv4; i += stride)
            __stcs(o4 + i, zf4);
        if (zb == 0 && tid == 0) {
            for (long long i = (nv4 << 2); i < out_n; i++) out[i] = 0.f;
        }
        return;
    }

    __shared__ __align__(16) float xs[2][32][XST];
    __shared__ __align__(16) float ws[2][32][XST];

    const int kp = blockIdx.x & 3;
    const int tb = blockIdx.x >> 2;
    const int t0 = tb * 64;
    const int kbase = kp * 1024;

    const int tm = tid & 7;
    const int tn = tid >> 3;

    {
#pragma unroll
        for (int r = 0; r < 4; r++) {
            int idx = tid + r * 128;
            int row = idx >> 3;
            int kq  = (idx & 7) << 2;
            float4 xv = *reinterpret_cast<const float4*>(&x[(size_t)(t0 + row) * D + kbase + kq]);
            xs[0][kq + 0][row] = xv.x; xs[0][kq + 1][row] = xv.y;
            xs[0][kq + 2][row] = xv.z; xs[0][kq + 3][row] = xv.w;
            float4 wv = *reinterpret_cast<const float4*>(&w[(size_t)row * D + kbase + kq]);
            ws[0][kq + 0][row] = wv.x; ws[0][kq + 1][row] = wv.y;
            ws[0][kq + 2][row] = wv.z; ws[0][kq + 3][row] = wv.w;
        }
    }
    __syncthreads();

    unsigned long long acc[4][4];
#pragma unroll
    for (int i = 0; i < 4; i++)
#pragma unroll
        for (int j = 0; j < 4; j++) acc[i][j] = 0ULL;

    const int NKB = 1024 / 32;
    for (int kb = 0; kb < NKB; kb++) {
        const int buf = kb & 1;
        float4 px[4], pw[4];
        if (kb + 1 < NKB) {
            const int k0 = kbase + (kb + 1) * 32;
#pragma unroll
            for (int r = 0; r < 4; r++) {
                int idx = tid + r * 128;
                int row = idx >> 3;
                int kq  = (idx & 7) << 2;
                px[r] = *reinterpret_cast<const float4*>(&x[(size_t)(t0 + row) * D + k0 + kq]);
                pw[r] = *reinterpret_cast<const float4*>(&w[(size_t)row * D + k0 + kq]);
            }
        }

        const float* xr = &xs[buf][0][8 * tm];
        const float* wr = &ws[buf][0][4 * tn];

        ulonglong2 A0 = *reinterpret_cast<const ulonglong2*>(xr);
        ulonglong2 A1 = *reinterpret_cast<const ulonglong2*>(xr + 4);
        float4     Wc = *reinterpret_cast<const float4*>(wr);

#pragma unroll
        for (int kk = 0; kk < 32; kk++) {
            ulonglong2 B0, B1; float4 Wn;
            if (kk < 31) {
                const float* xn = xr + (kk + 1) * XST;
                const float* wn = wr + (kk + 1) * XST;
                B0 = *reinterpret_cast<const ulonglong2*>(xn);
                B1 = *reinterpret_cast<const ulonglong2*>(xn + 4);
                Wn = *reinterpret_cast<const float4*>(wn);
            }
            {
                unsigned long long wp;
                wp = packdup(Wc.x);
                fma2(acc[0][0], A0.x, wp); fma2(acc[1][0], A0.y, wp);
                fma2(acc[2][0], A1.x, wp); fma2(acc[3][0], A1.y, wp);
                wp = packdup(Wc.y);
                fma2(acc[0][1], A0.x, wp); fma2(acc[1][1], A0.y, wp);
                fma2(acc[2][1], A1.x, wp); fma2(acc[3][1], A1.y, wp);
                wp = packdup(Wc.z);
                fma2(acc[0][2], A0.x, wp); fma2(acc[1][2], A0.y, wp);
                fma2(acc[2][2], A1.x, wp); fma2(acc[3][2], A1.y, wp);
                wp = packdup(Wc.w);
                fma2(acc[0][3], A0.x, wp); fma2(acc[1][3], A0.y, wp);
                fma2(acc[2][3], A1.x, wp); fma2(acc[3][3], A1.y, wp);
            }
            if (kk < 31) { A0 = B0; A1 = B1; Wc = Wn; }
        }

        if (kb + 1 < NKB) {
            const int nb = buf ^ 1;
#pragma unroll
            for (int r = 0; r < 4; r++) {
                int idx = tid + r * 128;
                int row = idx >> 3;
                int kq  = (idx & 7) << 2;
                xs[nb][kq + 0][row] = px[r].x; xs[nb][kq + 1][row] = px[r].y;
                xs[nb][kq + 2][row] = px[r].z; xs[nb][kq + 3][row] = px[r].w;
                ws[nb][kq + 0][row] = pw[r].x; ws[nb][kq + 1][row] = pw[r].y;
                ws[nb][kq + 2][row] = pw[r].z; ws[nb][kq + 3][row] = pw[r].w;
            }
        }
        __syncthreads();
    }

    float* part = &g_part[(size_t)kp * SE];
#pragma unroll
    for (int i = 0; i < 4; i++) {
#pragma unroll
        for (int j = 0; j < 4; j++) {
            float lo, hi;
            unpack2(acc[i][j], lo, hi);
            int t = t0 + 8 * tm + 2 * i;
            int e = 4 * tn + j;
            part[(size_t)t * E + e]       = lo;
            part[(size_t)(t + 1) * E + e] = hi;
        }
    }
}

// ==========================================================================
// K23 (persistent, 65 blocks x 256 threads, one per SM — barrier-safe):
//   phase A: blocks 0..63 gate 128 tokens each (softmax+argmax+colsum+count)
//   --- 65-block ticket barrier ---
//   phase B: blocks 0..63 per-expert top-CAP select -> direct output writes;
//            block 64 writes exp_counts + l_aux.
// ==========================================================================
__global__ __launch_bounds__(256) void k23_gate_select(const float* __restrict__ noise,
                                                       float* __restrict__ out) {
    const int tid = threadIdx.x;
    const int bid = blockIdx.x;
    const int lane = tid & 31;
    const int wid = tid >> 5;

    __shared__ unsigned bits[K3_SMEM_CAP];
    __shared__ unsigned short tok[K3_SMEM_CAP];
    __shared__ int red[8];
    __shared__ int weq[8], wkp[8];
    __shared__ int sh_ne;
    __shared__ float cs[64];
    __shared__ int   cnt[64];
    __shared__ float contrib[64];

    // =================== phase A: gate (blocks 0..63) ===================
    if (bid < 64) {
        if (tid < 64) { cs[tid] = 0.f; cnt[tid] = 0; }
        __syncthreads();

#pragma unroll
        for (int it = 0; it < 16; it++) {
            const int t = bid * 128 + it * 8 + wid;
            const size_t b = (size_t)t * E;
            float l0 = 0.f, l1 = 0.f;
#pragma unroll
            for (int p = 0; p < 4; p++) {
                l0 += g_part[(size_t)p * SE + b + lane];
                l1 += g_part[(size_t)p * SE + b + 32 + lane];
            }
            float bv; int bi;
            if (l0 >= l1) { bv = l0; bi = lane; } else { bv = l1; bi = lane + 32; }
#pragma unroll
            for (int o = 16; o; o >>= 1) {
                float ov = __shfl_xor_sync(0xFFFFFFFFu, bv, o);
                int   oi = __shfl_xor_sync(0xFFFFFFFFu, bi, o);
                if (ov > bv || (ov == bv && oi < bi)) { bv = ov; bi = oi; }
            }
            float e0 = __expf(l0 - bv), e1 = __expf(l1 - bv);
            float z = e0 + e1;
#pragma unroll
            for (int o = 16; o; o >>= 1) z += __shfl_xor_sync(0xFFFFFFFFu, z, o);
            float inv = 1.0f / z;

            atomicAdd(&cs[lane],      e0 * inv);
            atomicAdd(&cs[lane + 32], e1 * inv);
            if (lane == 0) {
                g_assign[t]  = bi;
                g_topgate[t] = inv;
                atomicAdd(&cnt[bi], 1);
            }
        }
        __syncthreads();
        if (tid < 64) {
            g_cspart[bid * 64 + tid] = cs[tid];
            if (cnt[tid]) atomicAdd(&g_counts[tid], cnt[tid]);
        }
    }

    // ---- 65-block barrier (monotonic ticket: replay-safe, no reset) ----
    __syncthreads();
    if (tid == 0) {
        __threadfence();
        unsigned long long t = atomicAdd(&g_bar65, 1ULL);
        unsigned long long target = (t / 65ULL + 1ULL) * 65ULL;
        while (*((volatile unsigned long long*)&g_bar65) < target) { __nanosleep(64); }
        __threadfence();
    }
    __syncthreads();

    // =================== phase B ===================
    if (bid == 64) {
        // ---- exp_counts + l_aux ----
        if (tid < 64) {
            float s = 0.f;
            for (int bkt = 0; bkt < 64; bkt++) s += g_cspart[bkt * 64 + tid];
            float me = s / (float)S;
            float ce = (float)g_counts[tid] / (float)S;
            contrib[tid] = me * ce * (float)E;
            out[1 + 2 * SEC + tid] = (float)g_counts[tid];
        }
        __syncthreads();
        if (tid == 0) {
            float l = 0.f;
            for (int i = 0; i < 64; i++) l += contrib[i];
            out[0] = l;
        }
        return;
    }

    const int e = bid;

    // ---- pass 1: ordered compaction ----
    int base = 0;
    for (int c0 = 0; c0 < S; c0 += 256) {
        const int t = c0 + tid;
        const bool a = (g_assign[t] == e);
        unsigned b = 0u;
        if (a) b = __float_as_uint(noise[(size_t)t * E + e]);
        unsigned bal = __ballot_sync(0xFFFFFFFFu, a);
        if (lane == 0) red[wid] = __popc(bal);
        __syncthreads();
        int off = 0;
        for (int i = 0; i < wid; i++) off += red[i];
        int tot = 0;
#pragma unroll
        for (int i = 0; i < 8; i++) tot += red[i];
        if (a) {
            int pos = base + off + __popc(bal & ((1u << lane) - 1u));
            if (pos < K3_SMEM_CAP) {
                bits[pos] = b;
                tok[pos]  = (unsigned short)t;
            }
        }
        base += tot;
        __syncthreads();
    }
    if (tid == 0) sh_ne = base;
    __syncthreads();
    const int ne = sh_ne;
    const bool smem_ok = (ne <= K3_SMEM_CAP);

    // ---- pass 2: binary search for threshold T ----
    unsigned lo = 0u, hi = 0x3F7FFFFFu;
    while (lo < hi) {
        unsigned mid = lo + ((hi - lo + 1) >> 1);
        int c = 0;
        if (smem_ok) {
            for (int i = tid; i < ne; i += 256) c += (bits[i] >= mid);
        } else {
            for (int t = tid; t < S; t += 256)
                if (g_assign[t] == e)
                    c += (__float_as_uint(noise[(size_t)t * E + e]) >= mid);
        }
#pragma unroll
        for (int o = 16; o; o >>= 1) c += __shfl_xor_sync(0xFFFFFFFFu, c, o);
        if (lane == 0) red[wid] = c;
        __syncthreads();
        int tot = 0;
#pragma unroll
        for (int i = 0; i < 8; i++) tot += red[i];
        __syncthreads();
        if (tot >= CAP) lo = mid; else hi = mid - 1;
    }
    const unsigned T = lo;

    // ---- pass 3: count strictly-greater ----
    int kg;
    {
        int c = 0;
        const unsigned q = T + 1u;
        if (smem_ok) {
            for (int i = tid; i < ne; i += 256) c += (bits[i] >= q);
        } else {
            for (int t = tid; t < S; t += 256)
                if (g_assign[t] == e)
                    c += (__float_as_uint(noise[(size_t)t * E + e]) >= q);
        }
#pragma unroll
        for (int o = 16; o; o >>= 1) c += __shfl_xor_sync(0xFFFFFFFFu, c, o);
        if (lane == 0) red[wid] = c;
        __syncthreads();
        int tot = 0;
#pragma unroll
        for (int i = 0; i < 8; i++) tot += red[i];
        kg = tot;
        __syncthreads();
    }
    const int remaining = CAP - kg;

    if (smem_ok && T > 0u) {
        // ---- pass 4 (fast): ordered walk of compacted list ----
        int kbase = 0, eqbase = 0;
        const int chunks = (ne + 255) >> 8;
        for (int ch = 0; ch < chunks; ch++) {
            const int i = ch * 256 + tid;
            const bool valid = (i < ne);
            unsigned v = valid ? bits[i] : 0u;
            const bool gt = valid && (v > T);
            const bool eq = valid && (v == T);

            unsigned beq = __ballot_sync(0xFFFFFFFFu, eq);
            if (lane == 0) weq[wid] = __popc(beq);
            __syncthreads();
            int eqoff = 0;
            for (int k = 0; k < wid; k++) eqoff += weq[k];
            int eqtot = 0;
#pragma unroll
            for (int k = 0; k < 8; k++) eqtot += weq[k];
            const int eqrank = eqbase + eqoff + __popc(beq & ((1u << lane) - 1u));

            const bool kept = gt || (eq && eqrank < remaining);
            unsigned bk = __ballot_sync(0xFFFFFFFFu, kept);
            if (lane == 0) wkp[wid] = __popc(bk);
            __syncthreads();
            int koff = 0;
            for (int k = 0; k < wid; k++) koff += wkp[k];
            int ktot = 0;
#pragma unroll
            for (int k = 0; k < 8; k++) ktot += wkp[k];

            if (kept) {
                const int slot = kbase + koff + __popc(bk & ((1u << lane) - 1u));
                const int t = tok[i];
                const long long off = ((long long)t * E + e) * (long long)CAP + slot;
                out[1 + off]       = g_topgate[t];
                out[1 + SEC + off] = 1.0f;
            }
            kbase  += ktot;
            eqbase += eqtot;
            __syncthreads();
        }
    } else {
        // ---- pass 4 (general): full scan; T==0 ties include unassigned ----
        int kbase = 0, eqbase = 0;
        for (int c0 = 0; c0 < S; c0 += 256) {
            const int t = c0 + tid;
            const bool a = (g_assign[t] == e);
            unsigned v = 0u;
            if (a) v = __float_as_uint(noise[(size_t)t * E + e]);
            const bool gt = a && (v > T);
            const bool eq = (v == T);

            unsigned beq = __ballot_sync(0xFFFFFFFFu, eq);
            if (lane == 0) weq[wid] = __popc(beq);
            __syncthreads();
            int eqoff = 0;
            for (int k = 0; k < wid; k++) eqoff += weq[k];
            int eqtot = 0;
#pragma unroll
            for (int k = 0; k < 8; k++) eqtot += weq[k];
            const int eqrank = eqbase + eqoff + __popc(beq & ((1u << lane) - 1u));

            const bool kept = a && (gt || (eq && eqrank < remaining));
            unsigned bk = __ballot_sync(0xFFFFFFFFu, kept);
            if (lane == 0) wkp[wid] = __popc(bk);
            __syncthreads();
            int koff = 0;
            for (int k = 0; k < wid; k++) koff += wkp[k];
            int ktot = 0;
#pragma unroll
            for (int k = 0; k < 8; k++) ktot += wkp[k];

            if (kept) {
                const int slot = kbase + koff + __popc(bk & ((1u << lane) - 1u));
                const long long off = ((long long)t * E + e) * (long long)CAP + slot;
                out[1 + off]       = g_topgate[t];
                out[1 + SEC + off] = 1.0f;
            }
            kbase  += ktot;
            eqbase += eqtot;
            __syncthreads();
        }
    }
}

// ==========================================================================
extern "C" void kernel_launch(void* const* d_in, const int* in_sizes, int n_in,
                              void* d_out, int out_size) {
    const float* x     = (const float*)d_in[0];
    const float* w     = (const float*)d_in[1];
    const float* noise = (const float*)d_in[2];
    float* out = (float*)d_out;
    const long long n = (long long)out_size;

    k1_fused<<<TOTAL_BLOCKS, 128>>>(x, w, out, n);
    k23_gate_select<<<65, 256>>>(noise, out);
}